// round 12
// baseline (speedup 1.0000x reference)
#include <cuda_runtime.h>
#include <math.h>

#define EPS 1e-8f
#define THREADS 512

// Per-op weights packed as two float4s (2x LDG.128 broadcast in main kernel).
__device__ float4 g_w4[2];

// Parallel weights kernel: 16 lanes each handle one column j, shfl-reduce.
// param ~ U[0,1) so softmax needs no max-subtraction (no overflow risk).
// Signals PDL dependents as soon as g_w4 is written.
__global__ void compute_weights_kernel(const float* __restrict__ param) {
    int lane = threadIdx.x;
    float c0 = 0.f, c1 = 0.f, c2 = 0.f, c3 = 0.f, c4 = 0.f, c5 = 0.f;
    if (lane < 16) {
        float e0 = __expf(__ldg(&param[0 * 16 + lane]));
        float e1 = __expf(__ldg(&param[1 * 16 + lane]));
        float e2 = __expf(__ldg(&param[2 * 16 + lane]));
        float e3 = __expf(__ldg(&param[3 * 16 + lane]));
        float e4 = __expf(__ldg(&param[4 * 16 + lane]));
        float e5 = __expf(__ldg(&param[5 * 16 + lane]));
        float inv = 1.0f / (((e0 + e1) + (e2 + e3)) + (e4 + e5));
        c0 = e0 * inv; c1 = e1 * inv; c2 = e2 * inv;
        c3 = e3 * inv; c4 = e4 * inv; c5 = e5 * inv;
    }
    #pragma unroll
    for (int off = 16; off > 0; off >>= 1) {
        c0 += __shfl_xor_sync(0xFFFFFFFFu, c0, off);
        c1 += __shfl_xor_sync(0xFFFFFFFFu, c1, off);
        c2 += __shfl_xor_sync(0xFFFFFFFFu, c2, off);
        c3 += __shfl_xor_sync(0xFFFFFFFFu, c3, off);
        c4 += __shfl_xor_sync(0xFFFFFFFFu, c4, off);
        c5 += __shfl_xor_sync(0xFFFFFFFFu, c5, off);
    }
    if (lane == 0) {
        g_w4[0] = make_float4(c0, c1, c2, c3);
        g_w4[1] = make_float4(c4, c5, 0.0f, 0.0f);
    }
    __syncwarp();
    asm volatile("griddepcontrol.launch_dependents;" ::: "memory");
}

__device__ __forceinline__ float fuse_op(float x, float y,
                                         float w0, float w1, float w2,
                                         float w3, float w4, float w5) {
    float ax = fabsf(x);
    float ay = fabsf(y);
    float sy = __sinf(y);
    float sx = __sinf(x);
    float d1 = __fdividef(x, ay + EPS);
    float d2 = __fdividef(y, ax + EPS);
    float r = w0 * (x + y);
    r = fmaf(w1, x * y, r);
    r = fmaf(w2, d1, r);
    r = fmaf(w3, d2, r);
    r = fmaf(w4, x * sy, r);
    r = fmaf(w5, y * sx, r);
    return r;
}

__device__ __forceinline__ float4 fuse4(float4 xv, float4 yv,
                                        float4 wa, float4 wb) {
    float4 o;
    o.x = fuse_op(xv.x, yv.x, wa.x, wa.y, wa.z, wa.w, wb.x, wb.y);
    o.y = fuse_op(xv.y, yv.y, wa.x, wa.y, wa.z, wa.w, wb.x, wb.y);
    o.z = fuse_op(xv.z, yv.z, wa.x, wa.y, wa.z, wa.w, wb.x, wb.y);
    o.w = fuse_op(xv.w, yv.w, wa.x, wa.y, wa.z, wa.w, wb.x, wb.y);
    return o;
}

// Exact-cover, PDL dependent: streaming loads issue BEFORE griddepcontrol.wait
// so the weights kernel hides under the first-wave DRAM latency.
__global__ void __launch_bounds__(THREADS)
fused_elementwise_exact(const float4* __restrict__ x4,
                        const float4* __restrict__ y4,
                        float4* __restrict__ out4) {
    unsigned int idx = blockIdx.x * THREADS + threadIdx.x;

    float4 xv = __ldcs(&x4[idx]);
    float4 yv = __ldcs(&y4[idx]);

    asm volatile("griddepcontrol.wait;" ::: "memory");
    float4 wa = g_w4[0];
    float4 wb = g_w4[1];

    __stcs(&out4[idx], fuse4(xv, yv, wa, wb));
}

// Guarded fallback for non-divisible n4 (also PDL-safe).
__global__ void __launch_bounds__(THREADS)
fused_elementwise_guarded(const float4* __restrict__ x4,
                          const float4* __restrict__ y4,
                          float4* __restrict__ out4,
                          unsigned int n4) {
    unsigned int idx = blockIdx.x * THREADS + threadIdx.x;
    asm volatile("griddepcontrol.wait;" ::: "memory");
    if (idx >= n4) return;
    float4 xv = __ldcs(&x4[idx]);
    float4 yv = __ldcs(&y4[idx]);
    float4 wa = g_w4[0];
    float4 wb = g_w4[1];
    __stcs(&out4[idx], fuse4(xv, yv, wa, wb));
}

// Scalar tail (n % 4 != 0 — not expected for this shape, but safe).
__global__ void fused_tail_kernel(const float* __restrict__ x,
                                  const float* __restrict__ y,
                                  float* __restrict__ out,
                                  long long start, long long n) {
    long long idx = start + (long long)blockIdx.x * blockDim.x + threadIdx.x;
    if (idx >= n) return;
    float4 wa = g_w4[0];
    float4 wb = g_w4[1];
    out[idx] = fuse_op(x[idx], y[idx], wa.x, wa.y, wa.z, wa.w, wb.x, wb.y);
}

extern "C" void kernel_launch(void* const* d_in, const int* in_sizes, int n_in,
                              void* d_out, int out_size) {
    const float* x = (const float*)d_in[0];
    const float* y = (const float*)d_in[1];
    const float* param = (const float*)d_in[2];
    float* out = (float*)d_out;

    long long n = (long long)in_sizes[0];  // 4*4096*4096 = 67108864
    long long n4ll = n / 4;
    long long tail_start = n4ll * 4;
    unsigned int n4 = (unsigned int)n4ll;

    compute_weights_kernel<<<1, 32>>>(param);

    cudaLaunchAttribute attr[1];
    attr[0].id = cudaLaunchAttributeProgrammaticStreamSerialization;
    attr[0].val.programmaticStreamSerializationAllowed = 1;

    cudaLaunchConfig_t cfg = {};
    cfg.blockDim = dim3(THREADS, 1, 1);
    cfg.dynamicSmemBytes = 0;
    cfg.stream = 0;
    cfg.attrs = attr;
    cfg.numAttrs = 1;

    if (n4 % THREADS == 0) {
        unsigned int blocks = n4 / THREADS;  // 32768 for this shape
        cfg.gridDim = dim3(blocks, 1, 1);
        cudaLaunchKernelEx(&cfg, fused_elementwise_exact,
                           (const float4*)x, (const float4*)y, (float4*)out);
    } else {
        unsigned int blocks = (n4 + THREADS - 1) / THREADS;
        cfg.gridDim = dim3(blocks, 1, 1);
        cudaLaunchKernelEx(&cfg, fused_elementwise_guarded,
                           (const float4*)x, (const float4*)y, (float4*)out, n4);
    }

    if (tail_start < n) {
        long long tail = n - tail_start;
        long long tblocks = (tail + 255) / 256;
        fused_tail_kernel<<<(unsigned)tblocks, 256>>>(x, y, out, tail_start, n);
    }
}

// round 13
// speedup vs baseline: 1.0176x; 1.0176x over previous
#include <cuda_runtime.h>
#include <math.h>

#define EPS 1e-8f
#define THREADS 256

// Per-op weights packed as two float4s (2x LDG.128 broadcast in main kernel).
__device__ float4 g_w4[2];

// Parallel weights kernel: 16 lanes each handle one column j, shfl-reduce.
// param ~ U[0,1) so softmax needs no max-subtraction (no overflow risk).
// Signals PDL dependents as soon as g_w4 is written.
__global__ void compute_weights_kernel(const float* __restrict__ param) {
    int lane = threadIdx.x;
    float c0 = 0.f, c1 = 0.f, c2 = 0.f, c3 = 0.f, c4 = 0.f, c5 = 0.f;
    if (lane < 16) {
        float e0 = __expf(__ldg(&param[0 * 16 + lane]));
        float e1 = __expf(__ldg(&param[1 * 16 + lane]));
        float e2 = __expf(__ldg(&param[2 * 16 + lane]));
        float e3 = __expf(__ldg(&param[3 * 16 + lane]));
        float e4 = __expf(__ldg(&param[4 * 16 + lane]));
        float e5 = __expf(__ldg(&param[5 * 16 + lane]));
        float inv = 1.0f / (((e0 + e1) + (e2 + e3)) + (e4 + e5));
        c0 = e0 * inv; c1 = e1 * inv; c2 = e2 * inv;
        c3 = e3 * inv; c4 = e4 * inv; c5 = e5 * inv;
    }
    #pragma unroll
    for (int off = 16; off > 0; off >>= 1) {
        c0 += __shfl_xor_sync(0xFFFFFFFFu, c0, off);
        c1 += __shfl_xor_sync(0xFFFFFFFFu, c1, off);
        c2 += __shfl_xor_sync(0xFFFFFFFFu, c2, off);
        c3 += __shfl_xor_sync(0xFFFFFFFFu, c3, off);
        c4 += __shfl_xor_sync(0xFFFFFFFFu, c4, off);
        c5 += __shfl_xor_sync(0xFFFFFFFFu, c5, off);
    }
    if (lane == 0) {
        g_w4[0] = make_float4(c0, c1, c2, c3);
        g_w4[1] = make_float4(c4, c5, 0.0f, 0.0f);
    }
    __syncwarp();
    // Writes before launch_dependents are visible to dependents after their
    // griddepcontrol.wait.
    asm volatile("griddepcontrol.launch_dependents;" ::: "memory");
}

__device__ __forceinline__ float fuse_op(float x, float y,
                                         float w0, float w1, float w2,
                                         float w3, float w4, float w5) {
    float ax = fabsf(x);
    float ay = fabsf(y);
    float sy = __sinf(y);
    float sx = __sinf(x);
    float d1 = __fdividef(x, ay + EPS);
    float d2 = __fdividef(y, ax + EPS);
    float r = w0 * (x + y);
    r = fmaf(w1, x * y, r);
    r = fmaf(w2, d1, r);
    r = fmaf(w3, d2, r);
    r = fmaf(w4, x * sy, r);
    r = fmaf(w5, y * sx, r);
    return r;
}

__device__ __forceinline__ float4 fuse4(float4 xv, float4 yv,
                                        float4 wa, float4 wb) {
    float4 o;
    o.x = fuse_op(xv.x, yv.x, wa.x, wa.y, wa.z, wa.w, wb.x, wb.y);
    o.y = fuse_op(xv.y, yv.y, wa.x, wa.y, wa.z, wa.w, wb.x, wb.y);
    o.z = fuse_op(xv.z, yv.z, wa.x, wa.y, wa.z, wa.w, wb.x, wb.y);
    o.w = fuse_op(xv.w, yv.w, wa.x, wa.y, wa.z, wa.w, wb.x, wb.y);
    return o;
}

// Exact-cover, PDL dependent: streaming loads issue BEFORE griddepcontrol.wait
// so the weights kernel hides under the first-wave DRAM latency.
__global__ void __launch_bounds__(THREADS)
fused_elementwise_exact(const float4* __restrict__ x4,
                        const float4* __restrict__ y4,
                        float4* __restrict__ out4) {
    unsigned int idx = blockIdx.x * THREADS + threadIdx.x;

    // Independent of the weights kernel — issue first.
    float4 xv = __ldcs(&x4[idx]);
    float4 yv = __ldcs(&y4[idx]);

    // Now wait for the primary grid (weights) to complete / flush.
    asm volatile("griddepcontrol.wait;" ::: "memory");
    float4 wa = g_w4[0];
    float4 wb = g_w4[1];

    __stcs(&out4[idx], fuse4(xv, yv, wa, wb));
}

// Guarded fallback for non-divisible n4 (also PDL-safe).
__global__ void __launch_bounds__(THREADS)
fused_elementwise_guarded(const float4* __restrict__ x4,
                          const float4* __restrict__ y4,
                          float4* __restrict__ out4,
                          unsigned int n4) {
    unsigned int idx = blockIdx.x * THREADS + threadIdx.x;
    asm volatile("griddepcontrol.wait;" ::: "memory");
    if (idx >= n4) return;
    float4 xv = __ldcs(&x4[idx]);
    float4 yv = __ldcs(&y4[idx]);
    float4 wa = g_w4[0];
    float4 wb = g_w4[1];
    __stcs(&out4[idx], fuse4(xv, yv, wa, wb));
}

// Scalar tail (n % 4 != 0 — not expected for this shape, but safe).
__global__ void fused_tail_kernel(const float* __restrict__ x,
                                  const float* __restrict__ y,
                                  float* __restrict__ out,
                                  long long start, long long n) {
    long long idx = start + (long long)blockIdx.x * blockDim.x + threadIdx.x;
    if (idx >= n) return;
    float4 wa = g_w4[0];
    float4 wb = g_w4[1];
    out[idx] = fuse_op(x[idx], y[idx], wa.x, wa.y, wa.z, wa.w, wb.x, wb.y);
}

extern "C" void kernel_launch(void* const* d_in, const int* in_sizes, int n_in,
                              void* d_out, int out_size) {
    const float* x = (const float*)d_in[0];
    const float* y = (const float*)d_in[1];
    const float* param = (const float*)d_in[2];
    float* out = (float*)d_out;

    long long n = (long long)in_sizes[0];  // 4*4096*4096 = 67108864
    long long n4ll = n / 4;
    long long tail_start = n4ll * 4;
    unsigned int n4 = (unsigned int)n4ll;

    compute_weights_kernel<<<1, 32>>>(param);

    // Main kernel launched with Programmatic Stream Serialization: it may
    // begin while the weights kernel is still resident; griddepcontrol.wait
    // inside provides the ordering on g_w4.
    cudaLaunchAttribute attr[1];
    attr[0].id = cudaLaunchAttributeProgrammaticStreamSerialization;
    attr[0].val.programmaticStreamSerializationAllowed = 1;

    cudaLaunchConfig_t cfg = {};
    cfg.blockDim = dim3(THREADS, 1, 1);
    cfg.dynamicSmemBytes = 0;
    cfg.stream = 0;
    cfg.attrs = attr;
    cfg.numAttrs = 1;

    if (n4 % THREADS == 0) {
        unsigned int blocks = n4 / THREADS;  // 65536 for this shape
        cfg.gridDim = dim3(blocks, 1, 1);
        cudaLaunchKernelEx(&cfg, fused_elementwise_exact,
                           (const float4*)x, (const float4*)y, (float4*)out);
    } else {
        unsigned int blocks = (n4 + THREADS - 1) / THREADS;
        cfg.gridDim = dim3(blocks, 1, 1);
        cudaLaunchKernelEx(&cfg, fused_elementwise_guarded,
                           (const float4*)x, (const float4*)y, (float4*)out, n4);
    }

    if (tail_start < n) {
        long long tail = n - tail_start;
        long long tblocks = (tail + 255) / 256;
        fused_tail_kernel<<<(unsigned)tblocks, 256>>>(x, y, out, tail_start, n);
    }
}